// round 7
// baseline (speedup 1.0000x reference)
#include <cuda_runtime.h>
#include <cuda_bf16.h>

// IoU_31336081391713: elementwise YOLO IoU.
// Inputs: cell_nos [N,2] i32, output [N,5,5] f32, target [N,5] f32 -> IoU [N,5] f32.
// Persistent-block, cp.async double-buffered + L2-prefetch streaming kernel.

#define YI 20.0f
#define TILE 128          // boxes per tile == threads per block
#define THREADS 128
#define NA 5
#define OUT_F (TILE * 25) // 3200 floats (12800 B -> 100 x 128B lines)
#define TGT_F (TILE * 5)  // 640 floats  (2560 B  -> 20 lines)
#define CELL_I (TILE * 2) // 256 ints    (1024 B  -> 8 lines)

__device__ __forceinline__ void cpa16(void* smem, const void* gmem) {
    unsigned s = (unsigned)__cvta_generic_to_shared(smem);
    asm volatile("cp.async.cg.shared.global [%0], [%1], 16;\n" :: "r"(s), "l"(gmem));
}
__device__ __forceinline__ void l2pf(const void* gmem) {
    asm volatile("prefetch.global.L2 [%0];\n" :: "l"(gmem));
}
#define CP_COMMIT() asm volatile("cp.async.commit_group;\n" ::: "memory")
#define CP_WAIT1()  asm volatile("cp.async.wait_group 1;\n" ::: "memory")

struct Buffers {
    float s_out[2][OUT_F];
    float s_tgt[2][TGT_F];
    int   s_cell[2][CELL_I];
    float s_res[TGT_F];
};

__device__ __forceinline__ void prefetch_tile(
    Buffers& B, int st, int tid, size_t b0, int nb,
    const int* __restrict__ g_cell,
    const float* __restrict__ g_out,
    const float* __restrict__ g_tgt)
{
    if (nb == TILE) {
        const float4* go4 = reinterpret_cast<const float4*>(g_out + b0 * 25);
        #pragma unroll
        for (int i = tid; i < OUT_F / 4; i += THREADS) cpa16(&B.s_out[st][i * 4], go4 + i);
        const float4* gt4 = reinterpret_cast<const float4*>(g_tgt + b0 * 5);
        #pragma unroll
        for (int i = tid; i < TGT_F / 4; i += THREADS) cpa16(&B.s_tgt[st][i * 4], gt4 + i);
        const int4* gc4 = reinterpret_cast<const int4*>(g_cell + b0 * 2);
        if (tid < CELL_I / 4) cpa16(&B.s_cell[st][tid * 4], gc4 + tid);
    } else {
        // guarded scalar tail (not hit for N=4M; kept for generality)
        for (int i = tid; i < nb * 25; i += THREADS) B.s_out[st][i]  = g_out[b0 * 25 + i];
        for (int i = tid; i < nb * 5;  i += THREADS) B.s_tgt[st][i]  = g_tgt[b0 * 5 + i];
        for (int i = tid; i < nb * 2;  i += THREADS) B.s_cell[st][i] = g_cell[b0 * 2 + i];
    }
}

__global__ __launch_bounds__(THREADS) void iou_kernel(
    const int*   __restrict__ g_cell,
    const float* __restrict__ g_out,
    const float* __restrict__ g_tgt,
    float*       __restrict__ g_res,
    int n_boxes, int n_tiles)
{
    __shared__ Buffers B;

    const int tid = threadIdx.x;
    const int G   = gridDim.x;

    // prologue: stage first tile into buffer 0
    {
        const int it = blockIdx.x;
        if (it < n_tiles) {
            const size_t b0 = (size_t)it * TILE;
            int nb = n_boxes - (int)b0; if (nb > TILE) nb = TILE;
            prefetch_tile(B, 0, tid, b0, nb, g_cell, g_out, g_tgt);
        }
    }
    CP_COMMIT();

    int st = 0;
    for (int it = blockIdx.x; it < n_tiles; it += G, st ^= 1) {
        // L2 prefetch for tile two strides ahead (fire-and-forget, full tiles only).
        // 128 lines of 128B per tile == exactly one prefetch per thread.
        {
            const int pt = it + 2 * G;
            if (pt >= 0 && (size_t)(pt + 1) * TILE <= (size_t)n_boxes) {
                const size_t pb0 = (size_t)pt * TILE;
                if (tid < 100) {
                    l2pf((const char*)(g_out + pb0 * 25) + (size_t)tid * 128);
                } else if (tid < 120) {
                    l2pf((const char*)(g_tgt + pb0 * 5) + (size_t)(tid - 100) * 128);
                } else {
                    l2pf((const char*)(g_cell + pb0 * 2) + (size_t)(tid - 120) * 128);
                }
            }
        }

        // stage next tile into the other buffer (overlaps wait+compute+store)
        const int nt = it + G;
        if (nt < n_tiles) {
            const size_t b0n = (size_t)nt * TILE;
            int nbn = n_boxes - (int)b0n; if (nbn > TILE) nbn = TILE;
            prefetch_tile(B, st ^ 1, tid, b0n, nbn, g_cell, g_out, g_tgt);
        }
        CP_COMMIT();
        CP_WAIT1();           // current buffer's group is complete
        __syncthreads();      // cross-thread visibility; also orders s_res reuse

        const size_t b0 = (size_t)it * TILE;
        int nb = n_boxes - (int)b0; if (nb > TILE) nb = TILE;

        if (tid < nb) {
            const float ci = (float)B.s_cell[st][tid * 2 + 0] * YI + YI * 0.5f;
            const float cj = (float)B.s_cell[st][tid * 2 + 1] * YI + YI * 0.5f;

            const float* t = &B.s_tgt[st][tid * 5];
            const float hg  = t[3] * YI;
            const float wg  = t[4] * YI;
            const float xcg = ci + t[1] * YI;
            const float ycg = cj + t[2] * YI;
            const float gx1 = ycg - wg * 0.5f;
            const float gy1 = xcg - hg * 0.5f;
            const float gx2 = ycg + wg * 0.5f;
            const float gy2 = xcg + hg * 0.5f;
            const float area_g = (gx2 - gx1) * (gy2 - gy1);

            const float* o = &B.s_out[st][tid * 25];
            #pragma unroll
            for (int a = 0; a < NA; a++) {
                const float* p = o + a * 5;
                const float h  = p[3] * YI;
                const float w  = p[4] * YI;
                const float xc = ci + p[1] * YI;
                const float yc = cj + p[2] * YI;
                const float px1 = yc - w * 0.5f;
                const float py1 = xc - h * 0.5f;
                const float px2 = yc + w * 0.5f;
                const float py2 = xc + h * 0.5f;
                const float area_p = (px2 - px1) * (py2 - py1);

                const float ltx = fmaxf(px1, gx1);
                const float lty = fmaxf(py1, gy1);
                const float rbx = fminf(px2, gx2);
                const float rby = fminf(py2, gy2);
                const float wx  = fmaxf(rbx - ltx, 0.0f);
                const float wy  = fmaxf(rby - lty, 0.0f);
                const float inter = wx * wy;
                const float uni   = area_p + area_g - inter;
                B.s_res[tid * 5 + a] = inter / uni;
            }
        }
        __syncthreads();

        if (nb == TILE) {
            float4* gr4 = reinterpret_cast<float4*>(g_res + b0 * 5);
            #pragma unroll
            for (int i = tid; i < TGT_F / 4; i += THREADS)
                __stcs(gr4 + i, reinterpret_cast<const float4*>(B.s_res)[i]);
        } else {
            for (int i = tid; i < nb * 5; i += THREADS) g_res[b0 * 5 + i] = B.s_res[i];
        }
        // next iteration's first __syncthreads orders s_res/buffer reuse
    }
}

extern "C" void kernel_launch(void* const* d_in, const int* in_sizes, int n_in,
                              void* d_out, int out_size) {
    const int*   cell = (const int*)d_in[0];
    const float* outp = (const float*)d_in[1];
    const float* tgt  = (const float*)d_in[2];
    float*       res  = (float*)d_out;

    const int n_boxes = in_sizes[0] / 2;
    const int n_tiles = (n_boxes + TILE - 1) / TILE;
    int grid = 152 * 6;               // persistent: 6 blocks/SM (35KB smem each)
    if (grid > n_tiles) grid = n_tiles;
    iou_kernel<<<grid, THREADS>>>(cell, outp, tgt, res, n_boxes, n_tiles);
}

// round 9
// speedup vs baseline: 1.0416x; 1.0416x over previous
#include <cuda_runtime.h>
#include <cuda_bf16.h>

// IoU_31336081391713: elementwise YOLO IoU.
// Inputs: cell_nos [N,2] i32, output [N,5,5] f32, target [N,5] f32 -> IoU [N,5] f32.
// Persistent-block, cp.async double-buffered streaming kernel (DRAM-bound).
// R7: TILE/THREADS doubled to 256 (half the barrier+loop overhead), dynamic smem,
//     3 blocks/SM -> same 24 warps/SM and 96KB reads in flight as the 94.7us R4.

#define YI 20.0f
#define TILE 256          // boxes per tile == threads per block
#define THREADS 256
#define NA 5
#define OUT_F (TILE * 25) // 6400 floats (25600 B)
#define TGT_F (TILE * 5)  // 1280 floats (5120 B)
#define CELL_I (TILE * 2) // 512 ints   (2048 B)

// dynamic smem layout (bytes)
#define OFF_OUT0 0
#define OFF_OUT1 (OFF_OUT0 + OUT_F * 4)
#define OFF_TGT0 (OFF_OUT1 + OUT_F * 4)
#define OFF_TGT1 (OFF_TGT0 + TGT_F * 4)
#define OFF_CEL0 (OFF_TGT1 + TGT_F * 4)
#define OFF_CEL1 (OFF_CEL0 + CELL_I * 4)
#define OFF_RES  (OFF_CEL1 + CELL_I * 4)
#define SMEM_BYTES (OFF_RES + TGT_F * 4)   // 70656 B

__device__ __forceinline__ void cpa16(void* smem, const void* gmem) {
    unsigned s = (unsigned)__cvta_generic_to_shared(smem);
    asm volatile("cp.async.cg.shared.global [%0], [%1], 16;\n" :: "r"(s), "l"(gmem));
}
#define CP_COMMIT() asm volatile("cp.async.commit_group;\n" ::: "memory")
#define CP_WAIT1()  asm volatile("cp.async.wait_group 1;\n" ::: "memory")

__device__ __forceinline__ void prefetch_tile(
    char* base, int st, int tid, size_t b0, int nb,
    const int* __restrict__ g_cell,
    const float* __restrict__ g_out,
    const float* __restrict__ g_tgt)
{
    float* s_out = (float*)(base + (st ? OFF_OUT1 : OFF_OUT0));
    float* s_tgt = (float*)(base + (st ? OFF_TGT1 : OFF_TGT0));
    int*   s_cel = (int*)  (base + (st ? OFF_CEL1 : OFF_CEL0));
    if (nb == TILE) {
        const float4* go4 = reinterpret_cast<const float4*>(g_out + b0 * 25);
        #pragma unroll
        for (int i = tid; i < OUT_F / 4; i += THREADS) cpa16(&s_out[i * 4], go4 + i);
        const float4* gt4 = reinterpret_cast<const float4*>(g_tgt + b0 * 5);
        #pragma unroll
        for (int i = tid; i < TGT_F / 4; i += THREADS) cpa16(&s_tgt[i * 4], gt4 + i);
        const int4* gc4 = reinterpret_cast<const int4*>(g_cell + b0 * 2);
        if (tid < CELL_I / 4) cpa16(&s_cel[tid * 4], gc4 + tid);
    } else {
        // guarded scalar tail (not hit for N=4M; kept for generality)
        for (int i = tid; i < nb * 25; i += THREADS) s_out[i] = g_out[b0 * 25 + i];
        for (int i = tid; i < nb * 5;  i += THREADS) s_tgt[i] = g_tgt[b0 * 5 + i];
        for (int i = tid; i < nb * 2;  i += THREADS) s_cel[i] = g_cell[b0 * 2 + i];
    }
}

__global__ __launch_bounds__(THREADS) void iou_kernel(
    const int*   __restrict__ g_cell,
    const float* __restrict__ g_out,
    const float* __restrict__ g_tgt,
    float*       __restrict__ g_res,
    int n_boxes, int n_tiles)
{
    extern __shared__ char base[];
    float* s_res = (float*)(base + OFF_RES);

    const int tid = threadIdx.x;
    const int G   = gridDim.x;

    // prologue: stage first tile into buffer 0
    {
        const int it = blockIdx.x;
        if (it < n_tiles) {
            const size_t b0 = (size_t)it * TILE;
            int nb = n_boxes - (int)b0; if (nb > TILE) nb = TILE;
            prefetch_tile(base, 0, tid, b0, nb, g_cell, g_out, g_tgt);
        }
    }
    CP_COMMIT();

    int st = 0;
    for (int it = blockIdx.x; it < n_tiles; it += G, st ^= 1) {
        // stage next tile into the other buffer (overlaps wait+compute+store)
        const int nt = it + G;
        if (nt < n_tiles) {
            const size_t b0n = (size_t)nt * TILE;
            int nbn = n_boxes - (int)b0n; if (nbn > TILE) nbn = TILE;
            prefetch_tile(base, st ^ 1, tid, b0n, nbn, g_cell, g_out, g_tgt);
        }
        CP_COMMIT();
        CP_WAIT1();           // current buffer's group is complete
        __syncthreads();      // cross-thread visibility; also orders s_res reuse

        const size_t b0 = (size_t)it * TILE;
        int nb = n_boxes - (int)b0; if (nb > TILE) nb = TILE;

        const float* s_out = (const float*)(base + (st ? OFF_OUT1 : OFF_OUT0));
        const float* s_tgt = (const float*)(base + (st ? OFF_TGT1 : OFF_TGT0));
        const int*   s_cel = (const int*)  (base + (st ? OFF_CEL1 : OFF_CEL0));

        if (tid < nb) {
            const float ci = (float)s_cel[tid * 2 + 0] * YI + YI * 0.5f;
            const float cj = (float)s_cel[tid * 2 + 1] * YI + YI * 0.5f;

            const float* t = &s_tgt[tid * 5];
            const float hg  = t[3] * YI;
            const float wg  = t[4] * YI;
            const float xcg = ci + t[1] * YI;
            const float ycg = cj + t[2] * YI;
            const float gx1 = ycg - wg * 0.5f;
            const float gy1 = xcg - hg * 0.5f;
            const float gx2 = ycg + wg * 0.5f;
            const float gy2 = xcg + hg * 0.5f;
            const float area_g = (gx2 - gx1) * (gy2 - gy1);

            const float* o = &s_out[tid * 25];
            #pragma unroll
            for (int a = 0; a < NA; a++) {
                const float* p = o + a * 5;
                const float h  = p[3] * YI;
                const float w  = p[4] * YI;
                const float xc = ci + p[1] * YI;
                const float yc = cj + p[2] * YI;
                const float px1 = yc - w * 0.5f;
                const float py1 = xc - h * 0.5f;
                const float px2 = yc + w * 0.5f;
                const float py2 = xc + h * 0.5f;
                const float area_p = (px2 - px1) * (py2 - py1);

                const float ltx = fmaxf(px1, gx1);
                const float lty = fmaxf(py1, gy1);
                const float rbx = fminf(px2, gx2);
                const float rby = fminf(py2, gy2);
                const float wx  = fmaxf(rbx - ltx, 0.0f);
                const float wy  = fmaxf(rby - lty, 0.0f);
                const float inter = wx * wy;
                const float uni   = area_p + area_g - inter;
                s_res[tid * 5 + a] = inter / uni;
            }
        }
        __syncthreads();      // s_res ready; trailing bar also guards buffer reuse

        if (nb == TILE) {
            float4* gr4 = reinterpret_cast<float4*>(g_res + b0 * 5);
            #pragma unroll
            for (int i = tid; i < TGT_F / 4; i += THREADS)
                __stcs(gr4 + i, reinterpret_cast<const float4*>(s_res)[i]);
        } else {
            for (int i = tid; i < nb * 5; i += THREADS) g_res[b0 * 5 + i] = s_res[i];
        }
    }
}

extern "C" void kernel_launch(void* const* d_in, const int* in_sizes, int n_in,
                              void* d_out, int out_size) {
    const int*   cell = (const int*)d_in[0];
    const float* outp = (const float*)d_in[1];
    const float* tgt  = (const float*)d_in[2];
    float*       res  = (float*)d_out;

    const int n_boxes = in_sizes[0] / 2;
    const int n_tiles = (n_boxes + TILE - 1) / TILE;

    cudaFuncSetAttribute(iou_kernel, cudaFuncAttributeMaxDynamicSharedMemorySize,
                         SMEM_BYTES);

    int grid = 152 * 3;               // persistent: 3 blocks/SM (69KB dyn smem each)
    if (grid > n_tiles) grid = n_tiles;
    iou_kernel<<<grid, THREADS, SMEM_BYTES>>>(cell, outp, tgt, res, n_boxes, n_tiles);
}